// round 15
// baseline (speedup 1.0000x reference)
#include <cuda_runtime.h>
#include <cuda_bf16.h>

// ---------------- problem constants ----------------
#define NGRAPH 500
#define NPG    100
#define EPG    800
#define NTOT   50000
#define ETOT   400000
#define KKEEP  640
#define KDROP  160

// output layout (floats), flattened tuple
#define OFF_CX    0
#define OFF_CEI   6400000
#define OFF_CATTR 7040000
#define OFF_CW    7360000
#define OFF_CB    7680000
#define OFF_FX    7730000
#define OFF_FEI   14130000
#define OFF_FATTR 14290000
#define OFF_FW    14370000
#define OFF_FB    14450000
#define OFF_ES    14500000

// ---------------- device scratch ----------------
__device__ float g_ABC[(size_t)NTOT * 384];     // [a|b|c] per node
__device__ float g_h1[(size_t)NTOT * 128];
__device__ float g_h[(size_t)NTOT * 128];
__device__ float g_U[(size_t)NTOT * 512];       // exact prefix chain k=0..127
__device__ float g_W1cat[64 * 384];
__device__ float g_W2cat[128 * 384];
__device__ float g_bias1[384];
__device__ float g_bias2[384];
__device__ float g_bz[512];
__device__ int   g_csr[ETOT];                   // local edge ids sorted (dst, edge id asc)
__device__ int   g_start[NGRAPH * 101];
__device__ float g_score[ETOT];
__device__ int   g_csrc[NGRAPH * KKEEP];
__device__ int   g_cdst[NGRAPH * KKEEP];
__device__ int   g_fsrc[NGRAPH * KDROP];
__device__ int   g_fdst[NGRAPH * KDROP];
__device__ unsigned g_cpres[NGRAPH * 4];
__device__ unsigned g_fpres[NGRAPH * 4];
__device__ int   g_ccnt[NGRAPH];
__device__ int   g_fcnt[NGRAPH];
__device__ int   g_coff[NGRAPH + 1];
__device__ int   g_foff[NGRAPH + 1];

// ---------------- f32x2 helpers (per-lane rounding == fmaf) ----------------
__device__ __forceinline__ unsigned long long pk2(float a) {
    unsigned long long r;
    asm("mov.b64 %0, {%1, %1};" : "=l"(r) : "f"(a));
    return r;
}
__device__ __forceinline__ void fma2(unsigned long long& d, unsigned long long a,
                                     unsigned long long b) {
    asm("fma.rn.f32x2 %0, %1, %2, %0;" : "+l"(d) : "l"(a), "l"(b));
}
__device__ __forceinline__ float2 unpk(unsigned long long v) {
    float lo, hi;
    asm("mov.b64 {%0, %1}, %2;" : "=f"(lo), "=f"(hi) : "l"(v));
    return make_float2(lo, hi);
}

// ---------------- prep: pack weights / biases ----------------
__global__ void k_prep(const float* __restrict__ c1w1, const float* __restrict__ c1b1,
                       const float* __restrict__ c1w2, const float* __restrict__ c1w3,
                       const float* __restrict__ c2w1, const float* __restrict__ c2b1,
                       const float* __restrict__ c2w2, const float* __restrict__ c2w3) {
    int idx = blockIdx.x * 256 + threadIdx.x;
    if (idx < 24576) {  // W1cat 64x384
        int k = idx / 384, j = idx - k * 384;
        g_W1cat[idx] = (j < 128) ? c1w1[k * 128 + j]
                     : (j < 256) ? c1w2[k * 128 + j - 128]
                                 : c1w3[k * 128 + j - 256];
        return;
    }
    idx -= 24576;
    if (idx < 49152) {  // W2cat 128x384
        int k = idx / 384, j = idx - k * 384;
        g_W2cat[idx] = (j < 128) ? c2w1[k * 128 + j]
                     : (j < 256) ? c2w2[k * 128 + j - 128]
                                 : c2w3[k * 128 + j - 256];
        return;
    }
    idx -= 49152;
    if (idx < 384) { g_bias1[idx] = (idx < 128) ? c1b1[idx] : 0.f; return; }
    idx -= 384;
    if (idx < 384) { g_bias2[idx] = (idx < 128) ? c2b1[idx] : 0.f; return; }
    idx -= 384;
    if (idx < 512) g_bz[idx] = 0.f;
}

// ---------------- CSR build (one CTA per graph, edge order preserved) --------
__global__ void k_csr(const int* __restrict__ ei) {
    __shared__ int dstl[EPG];
    __shared__ int cnt[NPG];
    __shared__ int start[NPG + 1];
    int g = blockIdx.x, tid = threadIdx.x;
    for (int e = tid; e < EPG; e += 128)
        dstl[e] = ei[ETOT + EPG * g + e] - NPG * g;
    __syncthreads();
    if (tid < NPG) {
        int c = 0;
        for (int e = 0; e < EPG; e++) c += (dstl[e] == tid);
        cnt[tid] = c;
    }
    __syncthreads();
    if (tid == 0) {
        int s = 0;
        for (int v = 0; v < NPG; v++) { start[v] = s; s += cnt[v]; }
        start[NPG] = s;
    }
    __syncthreads();
    if (tid < NPG) {
        int v = tid, pos = start[v];
        for (int e = 0; e < EPG; e++)
            if (dstl[e] == v) { g_csr[EPG * g + pos] = e; pos++; }
    }
    if (tid < NPG + 1) g_start[(NPG + 1) * g + tid] = start[tid];
}

// --------- GEMM: C = A@B + bias, ascending-k single-acc fma chain ----------
// A tile staged in smem; B read directly per-k (L2/L1-resident, coalesced).
template <int K>
__global__ __launch_bounds__(256) void k_gemm(
    const float* __restrict__ A, const float* __restrict__ B,
    const float* __restrict__ bias, float* __restrict__ C, int M, int N) {
    extern __shared__ float smem[];
    const int PK = K + 4;
    float* As = smem;                 // [128][K+4]
    int tid = threadIdx.x;
    int m0 = blockIdx.x * 128, n0 = blockIdx.y * 128;

    for (int idx = tid; idx < 128 * (K / 4); idx += 256) {
        int row = idx / (K / 4), q = (idx - row * (K / 4)) * 4;
        int gm = m0 + row;
        float4 v = make_float4(0.f, 0.f, 0.f, 0.f);
        if (gm < M) v = *(const float4*)&A[(size_t)gm * K + q];
        *(float4*)&As[row * PK + q] = v;
    }
    __syncthreads();

    int ty = tid >> 4, tx = tid & 15;
    float* asub = As + ty * 8 * PK;
    const float* Bp = B + n0 + tx * 8;
    unsigned long long acc[8][4];
#pragma unroll
    for (int i = 0; i < 8; i++)
#pragma unroll
        for (int j = 0; j < 4; j++) acc[i][j] = 0ull;

#pragma unroll 4
    for (int k = 0; k < K; k++) {
        unsigned long long a2[8], b2[4];
#pragma unroll
        for (int i = 0; i < 8; i++) a2[i] = pk2(asub[i * PK + k]);
#pragma unroll
        for (int j = 0; j < 4; j++)
            b2[j] = *(const unsigned long long*)&Bp[(size_t)k * N + 2 * j];
#pragma unroll
        for (int i = 0; i < 8; i++)
#pragma unroll
            for (int j = 0; j < 4; j++) fma2(acc[i][j], a2[i], b2[j]);
    }

#pragma unroll
    for (int i = 0; i < 8; i++) {
        int gm = m0 + ty * 8 + i;
        if (gm >= M) break;
        float* crow = C + (size_t)gm * N + n0 + tx * 8;
        const float* brow = bias + n0 + tx * 8;
#pragma unroll
        for (int j = 0; j < 4; j++) {
            float2 v = unpk(acc[i][j]);
            crow[2 * j]     = __fadd_rn(v.x, brow[2 * j]);
            crow[2 * j + 1] = __fadd_rn(v.y, brow[2 * j + 1]);
        }
    }
}

// ---- conv aggregation: per-edge msg, edge-ordered scatter-add (exact) ------
__global__ __launch_bounds__(512) void k_conv(
    const float* __restrict__ ABC, const int* __restrict__ ei,
    const float* __restrict__ attr, const float* __restrict__ b3,
    float* __restrict__ hout, int do_relu) {
    extern __shared__ float sm[];
    float* Aa = sm;                        // 100*128
    float* Bb = Aa + NPG * 128;            // 100*128
    float* ews = Bb + NPG * 128;           // 800
    int* srcl = (int*)(ews + EPG);         // 800
    int* csr_s = srcl + EPG;               // 800
    int* start_s = csr_s + EPG;            // 101
    int g = blockIdx.x, tid = threadIdx.x;
    int j = tid & 127, vs = tid >> 7;      // vs in 0..3

    for (int idx = tid; idx < NPG * 128; idx += 512) {
        int v = idx >> 7, j2 = idx & 127;
        size_t base = (size_t)(NPG * g + v) * 384;
        Aa[idx] = ABC[base + j2];
        Bb[idx] = ABC[base + 128 + j2];
    }
    for (int e = tid; e < EPG; e += 512) {
        int ge = EPG * g + e;
        srcl[e] = ei[ge] - NPG * g;
        ews[e] = attr[ge];
        csr_s[e] = g_csr[ge];
    }
    if (tid < NPG + 1) start_s[tid] = g_start[(NPG + 1) * g + tid];
    __syncthreads();

    float bj = b3[j];
    int v0 = vs * 25, v1 = v0 + 25;
    for (int v = v0; v < v1; v++) {
        float acc = 0.f;
        float Bv = Bb[v * 128 + j];
        int b = start_s[v], en = start_s[v + 1];
        for (int i = b; i < en; i++) {
            int e = csr_s[i];
            float m = __fmul_rn(__fsub_rn(Aa[srcl[e] * 128 + j], Bv), ews[e]);
            acc = __fadd_rn(acc, m);
        }
        float Cv = ABC[(size_t)(NPG * g + v) * 384 + 256 + j];
        float o = __fadd_rn(__fadd_rn(acc, Cv), bj);
        if (do_relu) o = fmaxf(o, 0.f);
        hout[(size_t)(NPG * g + v) * 128 + j] = o;
    }
}

// ---- edge scores --------------------------------------------------------
// Stage A: hidden = one ascending-k fma chain k=0..255 (U[src] prefix
// continued with dst features), + b1, relu. Stage B: 8 fma lanes (n mod 8),
// ascending n, carried across chunks; epilogue lo=(s0+s1)+(s2+s3),
// hi=(s4+s5)+(s6+s7), s=lo+hi, + b2. Identical arithmetic to R13.
// 64 edges/CTA; W1 dst-half read directly from gmem (L1-resident).
#define SPAD 132
#define EPC  64
__global__ __launch_bounds__(256) void k_score(
    const int* __restrict__ ei, const float* __restrict__ h,
    const float* __restrict__ U, const float* __restrict__ mw1,
    const float* __restrict__ mb1, const float* __restrict__ mw2,
    const float* __restrict__ mb2, float* __restrict__ out) {
    extern __shared__ float sm[];
    float* Adst = sm;                       // EPC*SPAD
    float* Ut = Adst + EPC * SPAD;          // EPC*SPAD (U chunk / hidden)
    float* w2s = Ut + EPC * SPAD;           // 128
    float* b1s = w2s + 128;                 // 128
    int* srcg = (int*)(b1s + 128);          // EPC

    int tid = threadIdx.x;
    int e0 = blockIdx.x * EPC;

    if (tid < EPC) srcg[tid] = ei[e0 + tid];
    // load Adst: EPC rows of h[dst] (full 128 features); 4 threads per row
    {
        int r = tid >> 2, q4 = tid & 3;
        int d = ei[ETOT + e0 + r];
        const float4* sp = (const float4*)(h + (size_t)d * 128) + q4 * 8;
        float4* dp = (float4*)(Adst + r * SPAD) + q4 * 8;
#pragma unroll
        for (int q = 0; q < 8; q++) dp[q] = sp[q];
    }

    int ty = tid >> 4, tx = tid & 15;
    float sacc[8];
#pragma unroll
    for (int t2 = 0; t2 < 8; t2++) sacc[t2] = 0.f;
    unsigned long long acc[4][4];

    for (int c = 0; c < 4; c++) {
        __syncthreads();
        // U chunk rows (per edge, by src); 4 threads per row
        {
            int r = tid >> 2, q4 = tid & 3;
            const float4* sp =
                (const float4*)(U + (size_t)srcg[r] * 512 + c * 128) + q4 * 8;
            float4* dp = (float4*)(Ut + r * SPAD) + q4 * 8;
#pragma unroll
            for (int q = 0; q < 8; q++) dp[q] = sp[q];
        }
        if (tid < 128) { w2s[tid] = mw2[c * 128 + tid]; b1s[tid] = mb1[c * 128 + tid]; }
        __syncthreads();

        // init acc from U prefix (own 4x8 region), continue ascending chain
        // with dst ks 0..127 (W1 dst half read direct from gmem)
#pragma unroll
        for (int i = 0; i < 4; i++)
#pragma unroll
            for (int j = 0; j < 4; j++)
                acc[i][j] = *(const unsigned long long*)
                    &Ut[(ty * 4 + i) * SPAD + tx * 8 + 2 * j];

        const float* mw1c = mw1 + (size_t)128 * 512 + c * 128 + tx * 8;
#pragma unroll 2
        for (int k = 0; k < 128; k++) {
            unsigned long long a2[4], w2p[4];
#pragma unroll
            for (int i = 0; i < 4; i++) a2[i] = pk2(Adst[(ty * 4 + i) * SPAD + k]);
            const float* wr = mw1c + (size_t)k * 512;
#pragma unroll
            for (int j = 0; j < 4; j++)
                w2p[j] = *(const unsigned long long*)&wr[2 * j];
#pragma unroll
            for (int i = 0; i < 4; i++)
#pragma unroll
                for (int j = 0; j < 4; j++) fma2(acc[i][j], a2[i], w2p[j]);
        }

        // hidden = relu(chain + b1) -> Ut
#pragma unroll
        for (int i = 0; i < 4; i++)
#pragma unroll
            for (int j = 0; j < 4; j++) {
                float2 v = unpk(acc[i][j]);
                int col = tx * 8 + 2 * j;
                Ut[(ty * 4 + i) * SPAD + col] =
                    fmaxf(__fadd_rn(v.x, b1s[col]), 0.f);
                Ut[(ty * 4 + i) * SPAD + col + 1] =
                    fmaxf(__fadd_rn(v.y, b1s[col + 1]), 0.f);
            }
        __syncthreads();

        // stage B: 8 fma accumulators, lane = n mod 8, ascending n
        if (tid < EPC) {
            const float* hr = Ut + tid * SPAD;
#pragma unroll 2
            for (int i = 0; i < 16; i++) {
#pragma unroll
                for (int j = 0; j < 8; j++)
                    sacc[j] = __fmaf_rn(hr[8 * i + j], w2s[8 * i + j], sacc[j]);
            }
        }
    }

    if (tid < EPC) {
        float lo = __fadd_rn(__fadd_rn(sacc[0], sacc[1]),
                             __fadd_rn(sacc[2], sacc[3]));
        float hi = __fadd_rn(__fadd_rn(sacc[4], sacc[5]),
                             __fadd_rn(sacc[6], sacc[7]));
        float s = __fadd_rn(__fadd_rn(lo, hi), mb2[0]);
        int ge = e0 + tid;
        g_score[ge] = s;
        out[OFF_ES + ge] = s;
    }
}

// ---------------- rank + split + presence (one CTA per graph) ----------------
__global__ void k_rank(const int* __restrict__ ei, const float* __restrict__ attr,
                       float* __restrict__ out) {
    __shared__ float s[EPG];
    __shared__ unsigned cm[4], fm[4];
    int g = blockIdx.x, e = threadIdx.x;
    s[e] = g_score[EPG * g + e];
    if (e < 4) { cm[e] = 0u; fm[e] = 0u; }
    __syncthreads();
    float se = s[e];
    int r = 0;
    for (int j = 0; j < EPG; j++) {
        float sj = s[j];
        if (sj > se || (sj == se && j < e)) r++;
    }
    int ge = EPG * g + e;
    int gs = ei[ge], gd = ei[ETOT + ge];
    float ae = attr[ge];
    int ls = gs - NPG * g, ld_ = gd - NPG * g;
    if (r < KKEEP) {
        int i = KKEEP * g + r;
        g_csrc[i] = gs; g_cdst[i] = gd;
        out[OFF_CATTR + i] = ae;
        out[OFF_CW + i] = se;
        atomicOr(&cm[ls >> 5], 1u << (ls & 31));
        atomicOr(&cm[ld_ >> 5], 1u << (ld_ & 31));
    } else {
        int i = KDROP * g + (r - KKEEP);
        g_fsrc[i] = gs; g_fdst[i] = gd;
        out[OFF_FATTR + i] = ae;
        out[OFF_FW + i] = -se;
        atomicOr(&fm[ls >> 5], 1u << (ls & 31));
        atomicOr(&fm[ld_ >> 5], 1u << (ld_ & 31));
    }
    __syncthreads();
    if (e < 4) { g_cpres[4 * g + e] = cm[e]; g_fpres[4 * g + e] = fm[e]; }
    if (e == 0) {
        g_ccnt[g] = __popc(cm[0]) + __popc(cm[1]) + __popc(cm[2]) + __popc(cm[3]);
        g_fcnt[g] = __popc(fm[0]) + __popc(fm[1]) + __popc(fm[2]) + __popc(fm[3]);
    }
}

// ---------------- exclusive scan of counts (single block) ----------------
__global__ void k_scan() {
    __shared__ int vals[512];
    int tid = threadIdx.x;
    vals[tid] = (tid < NGRAPH) ? g_ccnt[tid] : 0;
    __syncthreads();
    for (int off = 1; off < 512; off <<= 1) {
        int t = (tid >= off) ? vals[tid - off] : 0;
        __syncthreads();
        vals[tid] += t;
        __syncthreads();
    }
    if (tid == 0) g_coff[0] = 0;
    if (tid < NGRAPH) g_coff[tid + 1] = vals[tid];
    __syncthreads();
    vals[tid] = (tid < NGRAPH) ? g_fcnt[tid] : 0;
    __syncthreads();
    for (int off = 1; off < 512; off <<= 1) {
        int t = (tid >= off) ? vals[tid - off] : 0;
        __syncthreads();
        vals[tid] += t;
        __syncthreads();
    }
    if (tid == 0) g_foff[0] = 0;
    if (tid < NGRAPH) g_foff[tid + 1] = vals[tid];
}

__device__ __forceinline__ int rank_below(const unsigned* m, int loc) {
    int w = loc >> 5, b = loc & 31;
    int r = 0;
    for (int k = 0; k < w; k++) r += __popc(m[k]);
    r += __popc(m[w] & ((1u << b) - 1u));
    return r;
}

// ---------------- relabel edge indices ----------------
__global__ void k_relabel(float* __restrict__ out) {
    int i = blockIdx.x * 256 + threadIdx.x;
    if (i >= ETOT) return;
    if (i < NGRAPH * KKEEP) {
        int g = i / KKEEP;
        const unsigned* m = &g_cpres[4 * g];
        int base = g_coff[g];
        int rs = rank_below(m, g_csrc[i] - NPG * g);
        int rd = rank_below(m, g_cdst[i] - NPG * g);
        out[OFF_CEI + i] = (float)(base + rs);
        out[OFF_CEI + NGRAPH * KKEEP + i] = (float)(base + rd);
    } else {
        int j = i - NGRAPH * KKEEP;
        int g = j / KDROP;
        const unsigned* m = &g_fpres[4 * g];
        int base = g_foff[g];
        int rs = rank_below(m, g_fsrc[j] - NPG * g);
        int rd = rank_below(m, g_fdst[j] - NPG * g);
        out[OFF_FEI + j] = (float)(base + rs);
        out[OFF_FEI + NGRAPH * KDROP + j] = (float)(base + rd);
    }
}

// ---------------- gather present-node features (one CTA per graph) -----------
__global__ void k_gather(float* __restrict__ out) {
    int g = blockIdx.x, f = threadIdx.x;  // 128 threads
    {
        unsigned mm[4] = {g_cpres[4 * g], g_cpres[4 * g + 1],
                          g_cpres[4 * g + 2], g_cpres[4 * g + 3]};
        int row = g_coff[g];
        for (int v = 0; v < NPG; v++) {
            if ((mm[v >> 5] >> (v & 31)) & 1u) {
                out[OFF_CX + (size_t)row * 128 + f] = g_h[(size_t)(NPG * g + v) * 128 + f];
                if (f == 0) out[OFF_CB + row] = (float)g;
                row++;
            }
        }
    }
    {
        unsigned mm[4] = {g_fpres[4 * g], g_fpres[4 * g + 1],
                          g_fpres[4 * g + 2], g_fpres[4 * g + 3]};
        int row = g_foff[g];
        for (int v = 0; v < NPG; v++) {
            if ((mm[v >> 5] >> (v & 31)) & 1u) {
                out[OFF_FX + (size_t)row * 128 + f] = g_h[(size_t)(NPG * g + v) * 128 + f];
                if (f == 0) out[OFF_FB + row] = (float)g;
                row++;
            }
        }
    }
}

// ---------------- fill padded tails ----------------
__global__ void k_fill(float* __restrict__ out) {
    int t = blockIdx.x * 256 + threadIdx.x;
    if (t >= NTOT * 128) return;
    int row = t >> 7;
    int ctot = g_coff[NGRAPH], ftot = g_foff[NGRAPH];
    if (row >= ctot) out[OFF_CX + t] = 0.f;
    if (row >= ftot) out[OFF_FX + t] = 0.f;
    if (t < NTOT) {
        if (t >= ctot) out[OFF_CB + t] = -1.f;
        if (t >= ftot) out[OFF_FB + t] = -1.f;
    }
}

// ---------------- launch ----------------
extern "C" void kernel_launch(void* const* d_in, const int* in_sizes, int n_in,
                              void* d_out, int out_size) {
    const float* x    = (const float*)d_in[0];
    const int*   ei   = (const int*)d_in[1];
    const float* attr = (const float*)d_in[2];
    const float* c1w1 = (const float*)d_in[4];
    const float* c1b1 = (const float*)d_in[5];
    const float* c1w2 = (const float*)d_in[6];
    const float* c1w3 = (const float*)d_in[7];
    const float* c1b3 = (const float*)d_in[8];
    const float* c2w1 = (const float*)d_in[9];
    const float* c2b1 = (const float*)d_in[10];
    const float* c2w2 = (const float*)d_in[11];
    const float* c2w3 = (const float*)d_in[12];
    const float* c2b3 = (const float*)d_in[13];
    const float* mw1  = (const float*)d_in[14];
    const float* mb1  = (const float*)d_in[15];
    const float* mw2  = (const float*)d_in[16];
    const float* mb2  = (const float*)d_in[17];
    float* out = (float*)d_out;

    float* ABC; cudaGetSymbolAddress((void**)&ABC, g_ABC);
    float* h1;  cudaGetSymbolAddress((void**)&h1, g_h1);
    float* h;   cudaGetSymbolAddress((void**)&h, g_h);
    float* U;   cudaGetSymbolAddress((void**)&U, g_U);
    float* W1c; cudaGetSymbolAddress((void**)&W1c, g_W1cat);
    float* W2c; cudaGetSymbolAddress((void**)&W2c, g_W2cat);
    float* b1v; cudaGetSymbolAddress((void**)&b1v, g_bias1);
    float* b2v; cudaGetSymbolAddress((void**)&b2v, g_bias2);
    float* bz;  cudaGetSymbolAddress((void**)&bz, g_bz);

    const int smem64  = 128 * 68 * 4;     // As only
    const int smem128 = 128 * 132 * 4;    // As only
    const int smemConv  = (NPG * 128 * 2 + EPG) * 4 + (EPG * 2 + NPG + 1) * 4;
    const int smemScore = (EPC * SPAD * 2 + 256) * 4 + EPC * 4;

    cudaFuncSetAttribute(k_gemm<64>, cudaFuncAttributeMaxDynamicSharedMemorySize, smem64);
    cudaFuncSetAttribute(k_gemm<128>, cudaFuncAttributeMaxDynamicSharedMemorySize, smem128);
    cudaFuncSetAttribute(k_conv, cudaFuncAttributeMaxDynamicSharedMemorySize, smemConv);
    cudaFuncSetAttribute(k_score, cudaFuncAttributeMaxDynamicSharedMemorySize, smemScore);

    k_prep<<<(75008 + 255) / 256, 256>>>(c1w1, c1b1, c1w2, c1w3, c2w1, c2b1, c2w2, c2w3);
    k_csr<<<NGRAPH, 128>>>(ei);

    dim3 g384((NTOT + 127) / 128, 3);
    k_gemm<64><<<g384, 256, smem64>>>(x, W1c, b1v, ABC, NTOT, 384);
    k_conv<<<NGRAPH, 512, smemConv>>>(ABC, ei, attr, c1b3, h1, 1);
    k_gemm<128><<<g384, 256, smem128>>>(h1, W2c, b2v, ABC, NTOT, 384);
    k_conv<<<NGRAPH, 512, smemConv>>>(ABC, ei, attr, c2b3, h, 0);

    dim3 g512((NTOT + 127) / 128, 4);
    k_gemm<128><<<g512, 256, smem128>>>(h, mw1, bz, U, NTOT, 512);

    k_score<<<ETOT / EPC, 256, smemScore>>>(ei, h, U, mw1, mb1, mw2, mb2, out);

    k_rank<<<NGRAPH, EPG>>>(ei, attr, out);
    k_scan<<<1, 512>>>();
    k_relabel<<<(ETOT + 255) / 256, 256>>>(out);
    k_gather<<<NGRAPH, 128>>>(out);
    k_fill<<<(NTOT * 128 + 255) / 256, 256>>>(out);
}

// round 16
// speedup vs baseline: 1.5887x; 1.5887x over previous
#include <cuda_runtime.h>
#include <cuda_bf16.h>

// ---------------- problem constants ----------------
#define NGRAPH 500
#define NPG    100
#define EPG    800
#define NTOT   50000
#define ETOT   400000
#define KKEEP  640
#define KDROP  160

// output layout (floats), flattened tuple
#define OFF_CX    0
#define OFF_CEI   6400000
#define OFF_CATTR 7040000
#define OFF_CW    7360000
#define OFF_CB    7680000
#define OFF_FX    7730000
#define OFF_FEI   14130000
#define OFF_FATTR 14290000
#define OFF_FW    14370000
#define OFF_FB    14450000
#define OFF_ES    14500000

// ---------------- device scratch ----------------
__device__ float g_ABC[(size_t)NTOT * 384];     // [a|b|c] per node
__device__ float g_h1[(size_t)NTOT * 128];
__device__ float g_h[(size_t)NTOT * 128];
__device__ float g_U[(size_t)NTOT * 512];       // exact prefix chain k=0..127
__device__ float g_W1cat[64 * 384];
__device__ float g_W2cat[128 * 384];
__device__ float g_bias1[384];
__device__ float g_bias2[384];
__device__ float g_bz[512];
__device__ int   g_csr[ETOT];                   // local edge ids sorted (dst, edge id asc)
__device__ int   g_start[NGRAPH * 101];
__device__ float g_score[ETOT];
__device__ int   g_csrc[NGRAPH * KKEEP];
__device__ int   g_cdst[NGRAPH * KKEEP];
__device__ int   g_fsrc[NGRAPH * KDROP];
__device__ int   g_fdst[NGRAPH * KDROP];
__device__ unsigned g_cpres[NGRAPH * 4];
__device__ unsigned g_fpres[NGRAPH * 4];
__device__ int   g_ccnt[NGRAPH];
__device__ int   g_fcnt[NGRAPH];
__device__ int   g_coff[NGRAPH + 1];
__device__ int   g_foff[NGRAPH + 1];

// ---------------- f32x2 helpers (per-lane rounding == fmaf) ----------------
__device__ __forceinline__ unsigned long long pk2(float a) {
    unsigned long long r;
    asm("mov.b64 %0, {%1, %1};" : "=l"(r) : "f"(a));
    return r;
}
__device__ __forceinline__ void fma2(unsigned long long& d, unsigned long long a,
                                     unsigned long long b) {
    asm("fma.rn.f32x2 %0, %1, %2, %0;" : "+l"(d) : "l"(a), "l"(b));
}
__device__ __forceinline__ float2 unpk(unsigned long long v) {
    float lo, hi;
    asm("mov.b64 {%0, %1}, %2;" : "=f"(lo), "=f"(hi) : "l"(v));
    return make_float2(lo, hi);
}

// ---------------- prep: pack weights / biases ----------------
__global__ void k_prep(const float* __restrict__ c1w1, const float* __restrict__ c1b1,
                       const float* __restrict__ c1w2, const float* __restrict__ c1w3,
                       const float* __restrict__ c2w1, const float* __restrict__ c2b1,
                       const float* __restrict__ c2w2, const float* __restrict__ c2w3) {
    int idx = blockIdx.x * 256 + threadIdx.x;
    if (idx < 24576) {  // W1cat 64x384
        int k = idx / 384, j = idx - k * 384;
        g_W1cat[idx] = (j < 128) ? c1w1[k * 128 + j]
                     : (j < 256) ? c1w2[k * 128 + j - 128]
                                 : c1w3[k * 128 + j - 256];
        return;
    }
    idx -= 24576;
    if (idx < 49152) {  // W2cat 128x384
        int k = idx / 384, j = idx - k * 384;
        g_W2cat[idx] = (j < 128) ? c2w1[k * 128 + j]
                     : (j < 256) ? c2w2[k * 128 + j - 128]
                                 : c2w3[k * 128 + j - 256];
        return;
    }
    idx -= 49152;
    if (idx < 384) { g_bias1[idx] = (idx < 128) ? c1b1[idx] : 0.f; return; }
    idx -= 384;
    if (idx < 384) { g_bias2[idx] = (idx < 128) ? c2b1[idx] : 0.f; return; }
    idx -= 384;
    if (idx < 512) g_bz[idx] = 0.f;
}

// ---------------- CSR build (one CTA per graph, edge order preserved) --------
__global__ void k_csr(const int* __restrict__ ei) {
    __shared__ int dstl[EPG];
    __shared__ int cnt[NPG];
    __shared__ int start[NPG + 1];
    int g = blockIdx.x, tid = threadIdx.x;
    for (int e = tid; e < EPG; e += 128)
        dstl[e] = ei[ETOT + EPG * g + e] - NPG * g;
    __syncthreads();
    if (tid < NPG) {
        int c = 0;
        for (int e = 0; e < EPG; e++) c += (dstl[e] == tid);
        cnt[tid] = c;
    }
    __syncthreads();
    if (tid == 0) {
        int s = 0;
        for (int v = 0; v < NPG; v++) { start[v] = s; s += cnt[v]; }
        start[NPG] = s;
    }
    __syncthreads();
    if (tid < NPG) {
        int v = tid, pos = start[v];
        for (int e = 0; e < EPG; e++)
            if (dstl[e] == v) { g_csr[EPG * g + pos] = e; pos++; }
    }
    if (tid < NPG + 1) g_start[(NPG + 1) * g + tid] = start[tid];
}

// --------- GEMM: C = A@B + bias, ascending-k single-acc fma chain ----------
// A tile in smem; B staged in 64-row smem chunks (accumulators carried
// across chunks => identical chain).
template <int K>
__global__ __launch_bounds__(256) void k_gemm(
    const float* __restrict__ A, const float* __restrict__ B,
    const float* __restrict__ bias, float* __restrict__ C, int M, int N) {
    extern __shared__ float smem[];
    const int PK = K + 4;
    float* As = smem;                 // [128][K+4]
    float* Bs = smem + 128 * PK;      // [64][128]
    int tid = threadIdx.x;
    int m0 = blockIdx.x * 128, n0 = blockIdx.y * 128;

    for (int idx = tid; idx < 128 * (K / 4); idx += 256) {
        int row = idx / (K / 4), q = (idx - row * (K / 4)) * 4;
        int gm = m0 + row;
        float4 v = make_float4(0.f, 0.f, 0.f, 0.f);
        if (gm < M) v = *(const float4*)&A[(size_t)gm * K + q];
        *(float4*)&As[row * PK + q] = v;
    }

    int ty = tid >> 4, tx = tid & 15;
    float* asub = As + ty * 8 * PK;
    float* bsub = Bs + tx * 8;
    unsigned long long acc[8][4];
#pragma unroll
    for (int i = 0; i < 8; i++)
#pragma unroll
        for (int j = 0; j < 4; j++) acc[i][j] = 0ull;

    for (int kh = 0; kh < K / 64; kh++) {
        __syncthreads();
        for (int idx = tid; idx < 64 * 32; idx += 256) {
            int row = idx >> 5, q = (idx & 31) * 4;
            *(float4*)&Bs[row * 128 + q] =
                *(const float4*)&B[(size_t)(kh * 64 + row) * N + n0 + q];
        }
        __syncthreads();
#pragma unroll 4
        for (int kk = 0; kk < 64; kk++) {
            int k = kh * 64 + kk;
            unsigned long long a2[8], b2[4];
#pragma unroll
            for (int i = 0; i < 8; i++) a2[i] = pk2(asub[i * PK + k]);
#pragma unroll
            for (int j = 0; j < 4; j++)
                b2[j] = *(const unsigned long long*)&bsub[kk * 128 + 2 * j];
#pragma unroll
            for (int i = 0; i < 8; i++)
#pragma unroll
                for (int j = 0; j < 4; j++) fma2(acc[i][j], a2[i], b2[j]);
        }
    }

#pragma unroll
    for (int i = 0; i < 8; i++) {
        int gm = m0 + ty * 8 + i;
        if (gm >= M) break;
        float* crow = C + (size_t)gm * N + n0 + tx * 8;
        const float* brow = bias + n0 + tx * 8;
#pragma unroll
        for (int j = 0; j < 4; j++) {
            float2 v = unpk(acc[i][j]);
            crow[2 * j]     = __fadd_rn(v.x, brow[2 * j]);
            crow[2 * j + 1] = __fadd_rn(v.y, brow[2 * j + 1]);
        }
    }
}

// ---- conv aggregation: per-edge msg, edge-ordered scatter-add (exact) ------
__global__ __launch_bounds__(512) void k_conv(
    const float* __restrict__ ABC, const int* __restrict__ ei,
    const float* __restrict__ attr, const float* __restrict__ b3,
    float* __restrict__ hout, int do_relu) {
    extern __shared__ float sm[];
    float* Aa = sm;                        // 100*128
    float* Bb = Aa + NPG * 128;            // 100*128
    float* ews = Bb + NPG * 128;           // 800
    int* srcl = (int*)(ews + EPG);         // 800
    int* csr_s = srcl + EPG;               // 800
    int* start_s = csr_s + EPG;            // 101
    int g = blockIdx.x, tid = threadIdx.x;
    int j = tid & 127, vs = tid >> 7;      // vs in 0..3

    for (int idx = tid; idx < NPG * 128; idx += 512) {
        int v = idx >> 7, j2 = idx & 127;
        size_t base = (size_t)(NPG * g + v) * 384;
        Aa[idx] = ABC[base + j2];
        Bb[idx] = ABC[base + 128 + j2];
    }
    for (int e = tid; e < EPG; e += 512) {
        int ge = EPG * g + e;
        srcl[e] = ei[ge] - NPG * g;
        ews[e] = attr[ge];
        csr_s[e] = g_csr[ge];
    }
    if (tid < NPG + 1) start_s[tid] = g_start[(NPG + 1) * g + tid];
    __syncthreads();

    float bj = b3[j];
    int v0 = vs * 25, v1 = v0 + 25;
    for (int v = v0; v < v1; v++) {
        float acc = 0.f;
        float Bv = Bb[v * 128 + j];
        int b = start_s[v], en = start_s[v + 1];
        for (int i = b; i < en; i++) {
            int e = csr_s[i];
            float m = __fmul_rn(__fsub_rn(Aa[srcl[e] * 128 + j], Bv), ews[e]);
            acc = __fadd_rn(acc, m);
        }
        float Cv = ABC[(size_t)(NPG * g + v) * 384 + 256 + j];
        float o = __fadd_rn(__fadd_rn(acc, Cv), bj);
        if (do_relu) o = fmaxf(o, 0.f);
        hout[(size_t)(NPG * g + v) * 128 + j] = o;
    }
}

// ---- edge scores --------------------------------------------------------
// Stage A: hidden = one ascending-k fma chain k=0..255 (U[src] prefix
// continued with dst features), + b1, relu. Stage B: 8 fma lanes (n mod 8),
// ascending n, carried across chunks; epilogue lo=(s0+s1)+(s2+s3),
// hi=(s4+s5)+(s6+s7), s=lo+hi, + b2. Identical arithmetic to R13/R14.
// 64 edges/CTA; W1 dst-half staged in two 64-row smem chunks.
#define SPAD 132
#define EPC  64
__global__ __launch_bounds__(256) void k_score(
    const int* __restrict__ ei, const float* __restrict__ h,
    const float* __restrict__ U, const float* __restrict__ mw1,
    const float* __restrict__ mb1, const float* __restrict__ mw2,
    const float* __restrict__ mb2, float* __restrict__ out) {
    extern __shared__ float sm[];
    float* Adst = sm;                       // EPC*SPAD
    float* Ut = Adst + EPC * SPAD;          // EPC*SPAD (U chunk / hidden)
    float* Wd = Ut + EPC * SPAD;            // 64*128
    float* w2s = Wd + 64 * 128;             // 128
    float* b1s = w2s + 128;                 // 128
    int* srcg = (int*)(b1s + 128);          // EPC

    int tid = threadIdx.x;
    int e0 = blockIdx.x * EPC;

    if (tid < EPC) srcg[tid] = ei[e0 + tid];
    // load Adst: EPC rows of h[dst] (full 128 features); 4 threads per row
    {
        int r = tid >> 2, q4 = tid & 3;
        int d = ei[ETOT + e0 + r];
        const float4* sp = (const float4*)(h + (size_t)d * 128) + q4 * 8;
        float4* dp = (float4*)(Adst + r * SPAD) + q4 * 8;
#pragma unroll
        for (int q = 0; q < 8; q++) dp[q] = sp[q];
    }

    int ty = tid >> 4, tx = tid & 15;
    float sacc[8];
#pragma unroll
    for (int t2 = 0; t2 < 8; t2++) sacc[t2] = 0.f;
    unsigned long long acc[4][4];

    for (int c = 0; c < 4; c++) {
        __syncthreads();
        // U chunk rows (per edge, by src); 4 threads per row
        {
            int r = tid >> 2, q4 = tid & 3;
            const float4* sp =
                (const float4*)(U + (size_t)srcg[r] * 512 + c * 128) + q4 * 8;
            float4* dp = (float4*)(Ut + r * SPAD) + q4 * 8;
#pragma unroll
            for (int q = 0; q < 8; q++) dp[q] = sp[q];
        }
        if (tid < 128) { w2s[tid] = mw2[c * 128 + tid]; b1s[tid] = mb1[c * 128 + tid]; }
        __syncthreads();

        // init acc from U prefix (own 4x8 region), continue ascending chain
        // with dst ks 0..127; W1 dst-half staged in two 64-row chunks
#pragma unroll
        for (int i = 0; i < 4; i++)
#pragma unroll
            for (int j = 0; j < 4; j++)
                acc[i][j] = *(const unsigned long long*)
                    &Ut[(ty * 4 + i) * SPAD + tx * 8 + 2 * j];

        for (int kh = 0; kh < 2; kh++) {
            __syncthreads();
            for (int idx = tid; idx < 64 * 32; idx += 256) {
                int k = idx >> 5, q = (idx & 31) * 4;
                *(float4*)&Wd[k * 128 + q] =
                    *(const float4*)&mw1[(size_t)(128 + kh * 64 + k) * 512 +
                                         c * 128 + q];
            }
            __syncthreads();
#pragma unroll 4
            for (int kk = 0; kk < 64; kk++) {
                int k = kh * 64 + kk;
                unsigned long long a2[4], w2p[4];
#pragma unroll
                for (int i = 0; i < 4; i++)
                    a2[i] = pk2(Adst[(ty * 4 + i) * SPAD + k]);
#pragma unroll
                for (int j = 0; j < 4; j++)
                    w2p[j] = *(const unsigned long long*)
                        &Wd[kk * 128 + tx * 8 + 2 * j];
#pragma unroll
                for (int i = 0; i < 4; i++)
#pragma unroll
                    for (int j = 0; j < 4; j++) fma2(acc[i][j], a2[i], w2p[j]);
            }
        }

        // hidden = relu(chain + b1) -> Ut (own region)
#pragma unroll
        for (int i = 0; i < 4; i++)
#pragma unroll
            for (int j = 0; j < 4; j++) {
                float2 v = unpk(acc[i][j]);
                int col = tx * 8 + 2 * j;
                Ut[(ty * 4 + i) * SPAD + col] =
                    fmaxf(__fadd_rn(v.x, b1s[col]), 0.f);
                Ut[(ty * 4 + i) * SPAD + col + 1] =
                    fmaxf(__fadd_rn(v.y, b1s[col + 1]), 0.f);
            }
        __syncthreads();

        // stage B: 8 fma accumulators, lane = n mod 8, ascending n
        if (tid < EPC) {
            const float* hr = Ut + tid * SPAD;
#pragma unroll 2
            for (int i = 0; i < 16; i++) {
#pragma unroll
                for (int j = 0; j < 8; j++)
                    sacc[j] = __fmaf_rn(hr[8 * i + j], w2s[8 * i + j], sacc[j]);
            }
        }
    }

    if (tid < EPC) {
        float lo = __fadd_rn(__fadd_rn(sacc[0], sacc[1]),
                             __fadd_rn(sacc[2], sacc[3]));
        float hi = __fadd_rn(__fadd_rn(sacc[4], sacc[5]),
                             __fadd_rn(sacc[6], sacc[7]));
        float s = __fadd_rn(__fadd_rn(lo, hi), mb2[0]);
        int ge = e0 + tid;
        g_score[ge] = s;
        out[OFF_ES + ge] = s;
    }
}

// ---------------- rank + split + presence (one CTA per graph) ----------------
__global__ void k_rank(const int* __restrict__ ei, const float* __restrict__ attr,
                       float* __restrict__ out) {
    __shared__ float s[EPG];
    __shared__ unsigned cm[4], fm[4];
    int g = blockIdx.x, e = threadIdx.x;
    s[e] = g_score[EPG * g + e];
    if (e < 4) { cm[e] = 0u; fm[e] = 0u; }
    __syncthreads();
    float se = s[e];
    int r = 0;
    for (int j = 0; j < EPG; j++) {
        float sj = s[j];
        if (sj > se || (sj == se && j < e)) r++;
    }
    int ge = EPG * g + e;
    int gs = ei[ge], gd = ei[ETOT + ge];
    float ae = attr[ge];
    int ls = gs - NPG * g, ld_ = gd - NPG * g;
    if (r < KKEEP) {
        int i = KKEEP * g + r;
        g_csrc[i] = gs; g_cdst[i] = gd;
        out[OFF_CATTR + i] = ae;
        out[OFF_CW + i] = se;
        atomicOr(&cm[ls >> 5], 1u << (ls & 31));
        atomicOr(&cm[ld_ >> 5], 1u << (ld_ & 31));
    } else {
        int i = KDROP * g + (r - KKEEP);
        g_fsrc[i] = gs; g_fdst[i] = gd;
        out[OFF_FATTR + i] = ae;
        out[OFF_FW + i] = -se;
        atomicOr(&fm[ls >> 5], 1u << (ls & 31));
        atomicOr(&fm[ld_ >> 5], 1u << (ld_ & 31));
    }
    __syncthreads();
    if (e < 4) { g_cpres[4 * g + e] = cm[e]; g_fpres[4 * g + e] = fm[e]; }
    if (e == 0) {
        g_ccnt[g] = __popc(cm[0]) + __popc(cm[1]) + __popc(cm[2]) + __popc(cm[3]);
        g_fcnt[g] = __popc(fm[0]) + __popc(fm[1]) + __popc(fm[2]) + __popc(fm[3]);
    }
}

// ---------------- exclusive scan of counts (single block) ----------------
__global__ void k_scan() {
    __shared__ int vals[512];
    int tid = threadIdx.x;
    vals[tid] = (tid < NGRAPH) ? g_ccnt[tid] : 0;
    __syncthreads();
    for (int off = 1; off < 512; off <<= 1) {
        int t = (tid >= off) ? vals[tid - off] : 0;
        __syncthreads();
        vals[tid] += t;
        __syncthreads();
    }
    if (tid == 0) g_coff[0] = 0;
    if (tid < NGRAPH) g_coff[tid + 1] = vals[tid];
    __syncthreads();
    vals[tid] = (tid < NGRAPH) ? g_fcnt[tid] : 0;
    __syncthreads();
    for (int off = 1; off < 512; off <<= 1) {
        int t = (tid >= off) ? vals[tid - off] : 0;
        __syncthreads();
        vals[tid] += t;
        __syncthreads();
    }
    if (tid == 0) g_foff[0] = 0;
    if (tid < NGRAPH) g_foff[tid + 1] = vals[tid];
}

__device__ __forceinline__ int rank_below(const unsigned* m, int loc) {
    int w = loc >> 5, b = loc & 31;
    int r = 0;
    for (int k = 0; k < w; k++) r += __popc(m[k]);
    r += __popc(m[w] & ((1u << b) - 1u));
    return r;
}

// ---------------- relabel edge indices ----------------
__global__ void k_relabel(float* __restrict__ out) {
    int i = blockIdx.x * 256 + threadIdx.x;
    if (i >= ETOT) return;
    if (i < NGRAPH * KKEEP) {
        int g = i / KKEEP;
        const unsigned* m = &g_cpres[4 * g];
        int base = g_coff[g];
        int rs = rank_below(m, g_csrc[i] - NPG * g);
        int rd = rank_below(m, g_cdst[i] - NPG * g);
        out[OFF_CEI + i] = (float)(base + rs);
        out[OFF_CEI + NGRAPH * KKEEP + i] = (float)(base + rd);
    } else {
        int j = i - NGRAPH * KKEEP;
        int g = j / KDROP;
        const unsigned* m = &g_fpres[4 * g];
        int base = g_foff[g];
        int rs = rank_below(m, g_fsrc[j] - NPG * g);
        int rd = rank_below(m, g_fdst[j] - NPG * g);
        out[OFF_FEI + j] = (float)(base + rs);
        out[OFF_FEI + NGRAPH * KDROP + j] = (float)(base + rd);
    }
}

// ---------------- gather present-node features (one CTA per graph) -----------
__global__ void k_gather(float* __restrict__ out) {
    int g = blockIdx.x, f = threadIdx.x;  // 128 threads
    {
        unsigned mm[4] = {g_cpres[4 * g], g_cpres[4 * g + 1],
                          g_cpres[4 * g + 2], g_cpres[4 * g + 3]};
        int row = g_coff[g];
        for (int v = 0; v < NPG; v++) {
            if ((mm[v >> 5] >> (v & 31)) & 1u) {
                out[OFF_CX + (size_t)row * 128 + f] = g_h[(size_t)(NPG * g + v) * 128 + f];
                if (f == 0) out[OFF_CB + row] = (float)g;
                row++;
            }
        }
    }
    {
        unsigned mm[4] = {g_fpres[4 * g], g_fpres[4 * g + 1],
                          g_fpres[4 * g + 2], g_fpres[4 * g + 3]};
        int row = g_foff[g];
        for (int v = 0; v < NPG; v++) {
            if ((mm[v >> 5] >> (v & 31)) & 1u) {
                out[OFF_FX + (size_t)row * 128 + f] = g_h[(size_t)(NPG * g + v) * 128 + f];
                if (f == 0) out[OFF_FB + row] = (float)g;
                row++;
            }
        }
    }
}

// ---------------- fill padded tails ----------------
__global__ void k_fill(float* __restrict__ out) {
    int t = blockIdx.x * 256 + threadIdx.x;
    if (t >= NTOT * 128) return;
    int row = t >> 7;
    int ctot = g_coff[NGRAPH], ftot = g_foff[NGRAPH];
    if (row >= ctot) out[OFF_CX + t] = 0.f;
    if (row >= ftot) out[OFF_FX + t] = 0.f;
    if (t < NTOT) {
        if (t >= ctot) out[OFF_CB + t] = -1.f;
        if (t >= ftot) out[OFF_FB + t] = -1.f;
    }
}

// ---------------- launch ----------------
extern "C" void kernel_launch(void* const* d_in, const int* in_sizes, int n_in,
                              void* d_out, int out_size) {
    const float* x    = (const float*)d_in[0];
    const int*   ei   = (const int*)d_in[1];
    const float* attr = (const float*)d_in[2];
    const float* c1w1 = (const float*)d_in[4];
    const float* c1b1 = (const float*)d_in[5];
    const float* c1w2 = (const float*)d_in[6];
    const float* c1w3 = (const float*)d_in[7];
    const float* c1b3 = (const float*)d_in[8];
    const float* c2w1 = (const float*)d_in[9];
    const float* c2b1 = (const float*)d_in[10];
    const float* c2w2 = (const float*)d_in[11];
    const float* c2w3 = (const float*)d_in[12];
    const float* c2b3 = (const float*)d_in[13];
    const float* mw1  = (const float*)d_in[14];
    const float* mb1  = (const float*)d_in[15];
    const float* mw2  = (const float*)d_in[16];
    const float* mb2  = (const float*)d_in[17];
    float* out = (float*)d_out;

    float* ABC; cudaGetSymbolAddress((void**)&ABC, g_ABC);
    float* h1;  cudaGetSymbolAddress((void**)&h1, g_h1);
    float* h;   cudaGetSymbolAddress((void**)&h, g_h);
    float* U;   cudaGetSymbolAddress((void**)&U, g_U);
    float* W1c; cudaGetSymbolAddress((void**)&W1c, g_W1cat);
    float* W2c; cudaGetSymbolAddress((void**)&W2c, g_W2cat);
    float* b1v; cudaGetSymbolAddress((void**)&b1v, g_bias1);
    float* b2v; cudaGetSymbolAddress((void**)&b2v, g_bias2);
    float* bz;  cudaGetSymbolAddress((void**)&bz, g_bz);

    const int smem64  = (128 * 68 + 64 * 128) * 4;   // 67,584
    const int smem128 = (128 * 132 + 64 * 128) * 4;  // 100,352
    const int smemConv  = (NPG * 128 * 2 + EPG) * 4 + (EPG * 2 + NPG + 1) * 4;
    const int smemScore = (EPC * SPAD * 2 + 64 * 128 + 256) * 4 + EPC * 4;

    cudaFuncSetAttribute(k_gemm<64>, cudaFuncAttributeMaxDynamicSharedMemorySize, smem64);
    cudaFuncSetAttribute(k_gemm<128>, cudaFuncAttributeMaxDynamicSharedMemorySize, smem128);
    cudaFuncSetAttribute(k_conv, cudaFuncAttributeMaxDynamicSharedMemorySize, smemConv);
    cudaFuncSetAttribute(k_score, cudaFuncAttributeMaxDynamicSharedMemorySize, smemScore);

    k_prep<<<(75008 + 255) / 256, 256>>>(c1w1, c1b1, c1w2, c1w3, c2w1, c2b1, c2w2, c2w3);
    k_csr<<<NGRAPH, 128>>>(ei);

    dim3 g384((NTOT + 127) / 128, 3);
    k_gemm<64><<<g384, 256, smem64>>>(x, W1c, b1v, ABC, NTOT, 384);
    k_conv<<<NGRAPH, 512, smemConv>>>(ABC, ei, attr, c1b3, h1, 1);
    k_gemm<128><<<g384, 256, smem128>>>(h1, W2c, b2v, ABC, NTOT, 384);
    k_conv<<<NGRAPH, 512, smemConv>>>(ABC, ei, attr, c2b3, h, 0);

    dim3 g512((NTOT + 127) / 128, 4);
    k_gemm<128><<<g512, 256, smem128>>>(h, mw1, bz, U, NTOT, 512);

    k_score<<<ETOT / EPC, 256, smemScore>>>(ei, h, U, mw1, mb1, mw2, mb2, out);

    k_rank<<<NGRAPH, EPG>>>(ei, attr, out);
    k_scan<<<1, 512>>>();
    k_relabel<<<(ETOT + 255) / 256, 256>>>(out);
    k_gather<<<NGRAPH, 128>>>(out);
    k_fill<<<(NTOT * 128 + 255) / 256, 256>>>(out);
}

// round 17
// speedup vs baseline: 1.7919x; 1.1279x over previous
#include <cuda_runtime.h>
#include <cuda_bf16.h>

// ---------------- problem constants ----------------
#define NGRAPH 500
#define NPG    100
#define EPG    800
#define NTOT   50000
#define ETOT   400000
#define KKEEP  640
#define KDROP  160

// output layout (floats), flattened tuple
#define OFF_CX    0
#define OFF_CEI   6400000
#define OFF_CATTR 7040000
#define OFF_CW    7360000
#define OFF_CB    7680000
#define OFF_FX    7730000
#define OFF_FEI   14130000
#define OFF_FATTR 14290000
#define OFF_FW    14370000
#define OFF_FB    14450000
#define OFF_ES    14500000

// ---------------- device scratch ----------------
__device__ float g_ABC[(size_t)NTOT * 384];
__device__ float g_h1[(size_t)NTOT * 128];
__device__ float g_h[(size_t)NTOT * 128];
__device__ float g_U[(size_t)NTOT * 512];
__device__ int   g_csr[ETOT];
__device__ int   g_start[NGRAPH * 101];
__device__ float g_score[ETOT];
__device__ int   g_csrc[NGRAPH * KKEEP];
__device__ int   g_cdst[NGRAPH * KKEEP];
__device__ int   g_fsrc[NGRAPH * KDROP];
__device__ int   g_fdst[NGRAPH * KDROP];
__device__ unsigned g_cpres[NGRAPH * 4];
__device__ unsigned g_fpres[NGRAPH * 4];
__device__ int   g_ccnt[NGRAPH];
__device__ int   g_fcnt[NGRAPH];
__device__ int   g_coff[NGRAPH + 1];
__device__ int   g_foff[NGRAPH + 1];

// ---------------- f32x2 helpers (per-lane rounding == fmaf) ----------------
__device__ __forceinline__ unsigned long long pk2(float a) {
    unsigned long long r;
    asm("mov.b64 %0, {%1, %1};" : "=l"(r) : "f"(a));
    return r;
}
__device__ __forceinline__ unsigned long long pkf2(float lo, float hi) {
    unsigned long long r;
    asm("mov.b64 %0, {%1, %2};" : "=l"(r) : "f"(lo), "f"(hi));
    return r;
}
__device__ __forceinline__ void fma2(unsigned long long& d, unsigned long long a,
                                     unsigned long long b) {
    asm("fma.rn.f32x2 %0, %1, %2, %0;" : "+l"(d) : "l"(a), "l"(b));
}
__device__ __forceinline__ float2 unpk(unsigned long long v) {
    float lo, hi;
    asm("mov.b64 {%0, %1}, %2;" : "=f"(lo), "=f"(hi) : "l"(v));
    return make_float2(lo, hi);
}

// --------- GEMM: C = A@B(+bias on tile 0), ascending-k single-acc fma chain --
// A tile smem (PK=K+6, conflict-free); B staged in 64-row swizzled chunks
// (pair p stored at p+(p>>4), 136-float rows -> conflict-free LDS.64).
template <int K>
__global__ __launch_bounds__(256) void k_gemm(
    const float* __restrict__ A, const float* __restrict__ p0,
    const float* __restrict__ p1, const float* __restrict__ p2,
    const float* __restrict__ p3, int ldb, int coloff_per_tile,
    const float* __restrict__ bias0, float* __restrict__ C, int N, int M) {
    extern __shared__ float smem[];
    const int PK = K + 6;
    float* As = smem;                  // [128][PK]
    float* Bs = smem + 128 * PK;       // [64][136] swizzled
    int tid = threadIdx.x;
    int by = blockIdx.y;
    int m0 = blockIdx.x * 128;
    const float* Bsel = (by == 0) ? p0 : (by == 1) ? p1 : (by == 2) ? p2 : p3;
    int coloff = coloff_per_tile * by;

    for (int idx = tid; idx < 128 * (K / 2); idx += 256) {
        int row = idx / (K / 2), q = idx - row * (K / 2);
        int gm = m0 + row;
        float2 v = make_float2(0.f, 0.f);
        if (gm < M) v = *(const float2*)&A[(size_t)gm * K + 2 * q];
        *(float2*)&As[row * PK + 2 * q] = v;
    }

    int ty = tid >> 4, tx = tid & 15;
    int boff = 8 * tx + 2 * (tx >> 2);
    float* asub = As + ty * 8 * PK;
    unsigned long long acc[8][4];
#pragma unroll
    for (int i = 0; i < 8; i++)
#pragma unroll
        for (int j = 0; j < 4; j++) acc[i][j] = 0ull;

    for (int kh = 0; kh < K / 64; kh++) {
        __syncthreads();
        for (int idx = tid; idx < 64 * 64; idx += 256) {
            int k = idx >> 6, p = idx & 63;
            float2 v = *(const float2*)
                &Bsel[(size_t)(kh * 64 + k) * ldb + coloff + 2 * p];
            *(float2*)&Bs[k * 136 + 2 * (p + (p >> 4))] = v;
        }
        __syncthreads();
#pragma unroll 4
        for (int kk = 0; kk < 64; kk++) {
            int k = kh * 64 + kk;
            unsigned long long a2[8], b2[4];
#pragma unroll
            for (int i = 0; i < 8; i++) a2[i] = pk2(asub[i * PK + k]);
#pragma unroll
            for (int j = 0; j < 4; j++)
                b2[j] = *(const unsigned long long*)&Bs[kk * 136 + boff + 2 * j];
#pragma unroll
            for (int i = 0; i < 8; i++)
#pragma unroll
                for (int j = 0; j < 4; j++) fma2(acc[i][j], a2[i], b2[j]);
        }
    }

#pragma unroll
    for (int i = 0; i < 8; i++) {
        int gm = m0 + ty * 8 + i;
        if (gm >= M) break;
        float* crow = C + (size_t)gm * N + by * 128 + tx * 8;
#pragma unroll
        for (int j = 0; j < 4; j++) {
            float2 v = unpk(acc[i][j]);
            if (by == 0 && bias0) {
                crow[2 * j]     = __fadd_rn(v.x, bias0[tx * 8 + 2 * j]);
                crow[2 * j + 1] = __fadd_rn(v.y, bias0[tx * 8 + 2 * j + 1]);
            } else {
                crow[2 * j] = v.x;
                crow[2 * j + 1] = v.y;
            }
        }
    }
}

// ---- conv aggregation (exact); build==1 also constructs CSR in-CTA ---------
__global__ __launch_bounds__(512) void k_conv(
    const float* __restrict__ ABC, const int* __restrict__ ei,
    const float* __restrict__ attr, const float* __restrict__ b3,
    float* __restrict__ hout, int do_relu, int build) {
    extern __shared__ float sm[];
    float* Aa = sm;                        // 100*128
    float* Bb = Aa + NPG * 128;            // 100*128
    float* ews = Bb + NPG * 128;           // 800
    int* srcl = (int*)(ews + EPG);         // 800
    int* csr_s = srcl + EPG;               // 800
    int* start_s = csr_s + EPG;            // 101
    int* dstl = start_s + NPG + 1;         // 800
    int* cnt = dstl + EPG;                 // 100
    int g = blockIdx.x, tid = threadIdx.x;
    int j = tid & 127, vs = tid >> 7;

    for (int idx = tid; idx < NPG * 128; idx += 512) {
        int v = idx >> 7, j2 = idx & 127;
        size_t base = (size_t)(NPG * g + v) * 384;
        Aa[idx] = ABC[base + j2];
        Bb[idx] = ABC[base + 128 + j2];
    }
    for (int e = tid; e < EPG; e += 512) {
        int ge = EPG * g + e;
        srcl[e] = ei[ge] - NPG * g;
        ews[e] = attr[ge];
    }
    if (build) {
        for (int e = tid; e < EPG; e += 512)
            dstl[e] = ei[ETOT + EPG * g + e] - NPG * g;
        __syncthreads();
        if (tid < NPG) {
            int c = 0;
            for (int e = 0; e < EPG; e++) c += (dstl[e] == tid);
            cnt[tid] = c;
        }
        __syncthreads();
        if (tid == 0) {
            int s = 0;
            for (int v = 0; v < NPG; v++) { start_s[v] = s; s += cnt[v]; }
            start_s[NPG] = s;
        }
        __syncthreads();
        if (tid < NPG) {
            int v = tid, pos = start_s[v];
            for (int e = 0; e < EPG; e++)
                if (dstl[e] == v) { csr_s[pos] = e; pos++; }
        }
        __syncthreads();
        for (int e = tid; e < EPG; e += 512) g_csr[EPG * g + e] = csr_s[e];
        if (tid < NPG + 1) g_start[(NPG + 1) * g + tid] = start_s[tid];
    } else {
        for (int e = tid; e < EPG; e += 512) csr_s[e] = g_csr[EPG * g + e];
        if (tid < NPG + 1) start_s[tid] = g_start[(NPG + 1) * g + tid];
        __syncthreads();
    }

    float bj = b3[j];
    int v0 = vs * 25, v1 = v0 + 25;
    for (int v = v0; v < v1; v++) {
        float acc = 0.f;
        float Bv = Bb[v * 128 + j];
        int b = start_s[v], en = start_s[v + 1];
        for (int i = b; i < en; i++) {
            int e = csr_s[i];
            float m = __fmul_rn(__fsub_rn(Aa[srcl[e] * 128 + j], Bv), ews[e]);
            acc = __fadd_rn(acc, m);
        }
        float Cv = ABC[(size_t)(NPG * g + v) * 384 + 256 + j];
        float o = __fadd_rn(__fadd_rn(acc, Cv), bj);
        if (do_relu) o = fmaxf(o, 0.f);
        hout[(size_t)(NPG * g + v) * 128 + j] = o;
    }
}

// ---- edge scores (R14 arithmetic, conflict-free layouts) -------------------
// Stage A: ascending-k fma chain k=0..255 (U prefix continued with dst ks).
// Stage B: 8 fma lanes (n mod 8), ascending n, carried; epilogue
// lo=(s0+s1)+(s2+s3), hi=(s4+s5)+(s6+s7), s=lo+hi, + b2.
#define SPAD 130
__global__ __launch_bounds__(256) void k_score(
    const int* __restrict__ ei, const float* __restrict__ h,
    const float* __restrict__ U, const float* __restrict__ mw1,
    const float* __restrict__ mb1, const float* __restrict__ mw2,
    const float* __restrict__ mb2, float* __restrict__ out) {
    extern __shared__ float sm[];
    float* Adst = sm;                       // 128*SPAD
    float* Ut = Adst + 128 * SPAD;          // 128*SPAD (U chunk / hidden)
    float* Wd = Ut + 128 * SPAD;            // 128*136 swizzled
    float* w2s = Wd + 128 * 136;            // 128
    float* b1s = w2s + 128;                 // 128
    int* srcg = (int*)(b1s + 128);          // 128

    int tid = threadIdx.x;
    int e0 = blockIdx.x * 128;

    if (tid < 128) srcg[tid] = ei[e0 + tid];
    {
        int r = tid >> 1, half = tid & 1;
        int d = ei[ETOT + e0 + r];
        const float4* sp = (const float4*)(h + (size_t)d * 128) + half * 16;
        float* dp = Adst + r * SPAD + half * 64;
#pragma unroll
        for (int q = 0; q < 16; q++) {
            float4 v = sp[q];
            *(float2*)(dp + 4 * q) = make_float2(v.x, v.y);
            *(float2*)(dp + 4 * q + 2) = make_float2(v.z, v.w);
        }
    }

    int ty = tid >> 4, tx = tid & 15;
    int boff = 8 * tx + 2 * (tx >> 2);
    float sacc[8];
#pragma unroll
    for (int t2 = 0; t2 < 8; t2++) sacc[t2] = 0.f;
    unsigned long long acc[8][4];

    for (int c = 0; c < 4; c++) {
        __syncthreads();
        {
            int r = tid >> 1, half = tid & 1;
            const float4* sp =
                (const float4*)(U + (size_t)srcg[r] * 512 + c * 128) + half * 16;
            float* dp = Ut + r * SPAD + half * 64;
#pragma unroll
            for (int q = 0; q < 16; q++) {
                float4 v = sp[q];
                *(float2*)(dp + 4 * q) = make_float2(v.x, v.y);
                *(float2*)(dp + 4 * q + 2) = make_float2(v.z, v.w);
            }
        }
        for (int idx = tid; idx < 128 * 64; idx += 256) {
            int k = idx >> 6, p = idx & 63;
            float2 v = *(const float2*)
                &mw1[(size_t)(128 + k) * 512 + c * 128 + 2 * p];
            *(float2*)&Wd[k * 136 + 2 * (p + (p >> 4))] = v;
        }
        if (tid < 128) { w2s[tid] = mw2[c * 128 + tid]; b1s[tid] = mb1[c * 128 + tid]; }
        __syncthreads();

#pragma unroll
        for (int i = 0; i < 8; i++)
#pragma unroll
            for (int j = 0; j < 4; j++)
                acc[i][j] = *(const unsigned long long*)
                    &Ut[(ty * 8 + i) * SPAD + tx * 8 + 2 * j];

#pragma unroll 2
        for (int k = 0; k < 128; k++) {
            unsigned long long a2[8], w2p[4];
#pragma unroll
            for (int i = 0; i < 8; i++) a2[i] = pk2(Adst[(ty * 8 + i) * SPAD + k]);
#pragma unroll
            for (int j = 0; j < 4; j++)
                w2p[j] = *(const unsigned long long*)&Wd[k * 136 + boff + 2 * j];
#pragma unroll
            for (int i = 0; i < 8; i++)
#pragma unroll
                for (int j = 0; j < 4; j++) fma2(acc[i][j], a2[i], w2p[j]);
        }

#pragma unroll
        for (int i = 0; i < 8; i++)
#pragma unroll
            for (int j = 0; j < 4; j++) {
                float2 v = unpk(acc[i][j]);
                int col = tx * 8 + 2 * j;
                float h0 = fmaxf(__fadd_rn(v.x, b1s[col]), 0.f);
                float h1 = fmaxf(__fadd_rn(v.y, b1s[col + 1]), 0.f);
                *(unsigned long long*)&Ut[(ty * 8 + i) * SPAD + col] =
                    pkf2(h0, h1);
            }
        __syncthreads();

        if (tid < 128) {
            const float* hr = Ut + tid * SPAD;
#pragma unroll 2
            for (int i = 0; i < 16; i++) {
#pragma unroll
                for (int j = 0; j < 8; j++)
                    sacc[j] = __fmaf_rn(hr[8 * i + j], w2s[8 * i + j], sacc[j]);
            }
        }
    }

    if (tid < 128) {
        float lo = __fadd_rn(__fadd_rn(sacc[0], sacc[1]),
                             __fadd_rn(sacc[2], sacc[3]));
        float hi = __fadd_rn(__fadd_rn(sacc[4], sacc[5]),
                             __fadd_rn(sacc[6], sacc[7]));
        float s = __fadd_rn(__fadd_rn(lo, hi), mb2[0]);
        int ge = e0 + tid;
        g_score[ge] = s;
        out[OFF_ES + ge] = s;
    }
}

// ---------------- rank + split + presence (one CTA per graph) ----------------
__global__ void k_rank(const int* __restrict__ ei, const float* __restrict__ attr,
                       float* __restrict__ out) {
    __shared__ float s[EPG];
    __shared__ unsigned cm[4], fm[4];
    int g = blockIdx.x, e = threadIdx.x;
    s[e] = g_score[EPG * g + e];
    if (e < 4) { cm[e] = 0u; fm[e] = 0u; }
    __syncthreads();
    float se = s[e];
    int r = 0;
    for (int j = 0; j < EPG; j++) {
        float sj = s[j];
        if (sj > se || (sj == se && j < e)) r++;
    }
    int ge = EPG * g + e;
    int gs = ei[ge], gd = ei[ETOT + ge];
    float ae = attr[ge];
    int ls = gs - NPG * g, ld_ = gd - NPG * g;
    if (r < KKEEP) {
        int i = KKEEP * g + r;
        g_csrc[i] = gs; g_cdst[i] = gd;
        out[OFF_CATTR + i] = ae;
        out[OFF_CW + i] = se;
        atomicOr(&cm[ls >> 5], 1u << (ls & 31));
        atomicOr(&cm[ld_ >> 5], 1u << (ld_ & 31));
    } else {
        int i = KDROP * g + (r - KKEEP);
        g_fsrc[i] = gs; g_fdst[i] = gd;
        out[OFF_FATTR + i] = ae;
        out[OFF_FW + i] = -se;
        atomicOr(&fm[ls >> 5], 1u << (ls & 31));
        atomicOr(&fm[ld_ >> 5], 1u << (ld_ & 31));
    }
    __syncthreads();
    if (e < 4) { g_cpres[4 * g + e] = cm[e]; g_fpres[4 * g + e] = fm[e]; }
    if (e == 0) {
        g_ccnt[g] = __popc(cm[0]) + __popc(cm[1]) + __popc(cm[2]) + __popc(cm[3]);
        g_fcnt[g] = __popc(fm[0]) + __popc(fm[1]) + __popc(fm[2]) + __popc(fm[3]);
    }
}

// ---------------- exclusive scan of counts (single block) ----------------
__global__ void k_scan() {
    __shared__ int vals[512];
    int tid = threadIdx.x;
    vals[tid] = (tid < NGRAPH) ? g_ccnt[tid] : 0;
    __syncthreads();
    for (int off = 1; off < 512; off <<= 1) {
        int t = (tid >= off) ? vals[tid - off] : 0;
        __syncthreads();
        vals[tid] += t;
        __syncthreads();
    }
    if (tid == 0) g_coff[0] = 0;
    if (tid < NGRAPH) g_coff[tid + 1] = vals[tid];
    __syncthreads();
    vals[tid] = (tid < NGRAPH) ? g_fcnt[tid] : 0;
    __syncthreads();
    for (int off = 1; off < 512; off <<= 1) {
        int t = (tid >= off) ? vals[tid - off] : 0;
        __syncthreads();
        vals[tid] += t;
        __syncthreads();
    }
    if (tid == 0) g_foff[0] = 0;
    if (tid < NGRAPH) g_foff[tid + 1] = vals[tid];
}

__device__ __forceinline__ int rank_below(const unsigned* m, int loc) {
    int w = loc >> 5, b = loc & 31;
    int r = 0;
    for (int k = 0; k < w; k++) r += __popc(m[k]);
    r += __popc(m[w] & ((1u << b) - 1u));
    return r;
}

// ---------------- relabel edge indices ----------------
__global__ void k_relabel(float* __restrict__ out) {
    int i = blockIdx.x * 256 + threadIdx.x;
    if (i >= ETOT) return;
    if (i < NGRAPH * KKEEP) {
        int g = i / KKEEP;
        const unsigned* m = &g_cpres[4 * g];
        int base = g_coff[g];
        int rs = rank_below(m, g_csrc[i] - NPG * g);
        int rd = rank_below(m, g_cdst[i] - NPG * g);
        out[OFF_CEI + i] = (float)(base + rs);
        out[OFF_CEI + NGRAPH * KKEEP + i] = (float)(base + rd);
    } else {
        int j = i - NGRAPH * KKEEP;
        int g = j / KDROP;
        const unsigned* m = &g_fpres[4 * g];
        int base = g_foff[g];
        int rs = rank_below(m, g_fsrc[j] - NPG * g);
        int rd = rank_below(m, g_fdst[j] - NPG * g);
        out[OFF_FEI + j] = (float)(base + rs);
        out[OFF_FEI + NGRAPH * KDROP + j] = (float)(base + rd);
    }
}

// ---------------- gather present-node features (fully parallel) -------------
__global__ void k_gather(float* __restrict__ out) {
    int idx = blockIdx.x * 256 + threadIdx.x;
    if (idx >= NTOT * 128) return;
    int nv = idx >> 7, f = idx & 127;
    int g = nv / NPG, v = nv - g * NPG;
    {
        const unsigned* m = &g_cpres[4 * g];
        if ((m[v >> 5] >> (v & 31)) & 1u) {
            int row = g_coff[g] + rank_below(m, v);
            out[OFF_CX + (size_t)row * 128 + f] = g_h[(size_t)nv * 128 + f];
            if (f == 0) out[OFF_CB + row] = (float)g;
        }
    }
    {
        const unsigned* m = &g_fpres[4 * g];
        if ((m[v >> 5] >> (v & 31)) & 1u) {
            int row = g_foff[g] + rank_below(m, v);
            out[OFF_FX + (size_t)row * 128 + f] = g_h[(size_t)nv * 128 + f];
            if (f == 0) out[OFF_FB + row] = (float)g;
        }
    }
}

// ---------------- fill padded tails ----------------
__global__ void k_fill(float* __restrict__ out) {
    int t = blockIdx.x * 256 + threadIdx.x;
    if (t >= NTOT * 128) return;
    int row = t >> 7;
    int ctot = g_coff[NGRAPH], ftot = g_foff[NGRAPH];
    if (row >= ctot) out[OFF_CX + t] = 0.f;
    if (row >= ftot) out[OFF_FX + t] = 0.f;
    if (t < NTOT) {
        if (t >= ctot) out[OFF_CB + t] = -1.f;
        if (t >= ftot) out[OFF_FB + t] = -1.f;
    }
}

// ---------------- launch ----------------
extern "C" void kernel_launch(void* const* d_in, const int* in_sizes, int n_in,
                              void* d_out, int out_size) {
    const float* x    = (const float*)d_in[0];
    const int*   ei   = (const int*)d_in[1];
    const float* attr = (const float*)d_in[2];
    const float* c1w1 = (const float*)d_in[4];
    const float* c1b1 = (const float*)d_in[5];
    const float* c1w2 = (const float*)d_in[6];
    const float* c1w3 = (const float*)d_in[7];
    const float* c1b3 = (const float*)d_in[8];
    const float* c2w1 = (const float*)d_in[9];
    const float* c2b1 = (const float*)d_in[10];
    const float* c2w2 = (const float*)d_in[11];
    const float* c2w3 = (const float*)d_in[12];
    const float* c2b3 = (const float*)d_in[13];
    const float* mw1  = (const float*)d_in[14];
    const float* mb1  = (const float*)d_in[15];
    const float* mw2  = (const float*)d_in[16];
    const float* mb2  = (const float*)d_in[17];
    float* out = (float*)d_out;

    float* ABC; cudaGetSymbolAddress((void**)&ABC, g_ABC);
    float* h1;  cudaGetSymbolAddress((void**)&h1, g_h1);
    float* h;   cudaGetSymbolAddress((void**)&h, g_h);
    float* U;   cudaGetSymbolAddress((void**)&U, g_U);

    const int smem64  = (128 * 70 + 64 * 136) * 4;    // 70,656
    const int smem128 = (128 * 134 + 64 * 136) * 4;   // 103,424
    const int smemConv  = (NPG * 128 * 2 + EPG) * 4 +
                          (EPG * 3 + NPG + 1 + NPG) * 4;
    const int smemScore = (128 * SPAD * 2 + 128 * 136 + 256) * 4 + 128 * 4;

    cudaFuncSetAttribute(k_gemm<64>, cudaFuncAttributeMaxDynamicSharedMemorySize, smem64);
    cudaFuncSetAttribute(k_gemm<128>, cudaFuncAttributeMaxDynamicSharedMemorySize, smem128);
    cudaFuncSetAttribute(k_conv, cudaFuncAttributeMaxDynamicSharedMemorySize, smemConv);
    cudaFuncSetAttribute(k_score, cudaFuncAttributeMaxDynamicSharedMemorySize, smemScore);

    dim3 g3(391, 3), g4(391, 4);
    // 1: layer-1 GEMM (weights read raw, bias c1b1 on tile 0)
    k_gemm<64><<<g3, 256, smem64>>>(x, c1w1, c1w2, c1w3, c1w3, 128, 0,
                                    c1b1, ABC, 384, NTOT);
    // 2: conv1 (builds CSR in-CTA, stores for conv2)
    k_conv<<<NGRAPH, 512, smemConv>>>(ABC, ei, attr, c1b3, h1, 1, 1);
    // 3: layer-2 GEMM
    k_gemm<128><<<g3, 256, smem128>>>(h1, c2w1, c2w2, c2w3, c2w3, 128, 0,
                                      c2b1, ABC, 384, NTOT);
    // 4: conv2
    k_conv<<<NGRAPH, 512, smemConv>>>(ABC, ei, attr, c2b3, h, 0, 0);
    // 5: U prefix GEMM (mw1 top half, 512 cols)
    k_gemm<128><<<g4, 256, smem128>>>(h, mw1, mw1, mw1, mw1, 512, 128,
                                      nullptr, U, 512, NTOT);
    // 6: edge scores (profiled slot)
    k_score<<<ETOT / 128, 256, smemScore>>>(ei, h, U, mw1, mb1, mw2, mb2, out);

    k_rank<<<NGRAPH, EPG>>>(ei, attr, out);
    k_scan<<<1, 512>>>();
    k_relabel<<<(ETOT + 255) / 256, 256>>>(out);
    k_gather<<<(NTOT * 128 + 255) / 256, 256>>>(out);
    k_fill<<<(NTOT * 128 + 255) / 256, 256>>>(out);
}